// round 1
// baseline (speedup 1.0000x reference)
#include <cuda_runtime.h>

// ---------------------------------------------------------------------------
// SelfAttention: x[4,2048,1024] -> out[4,2048,1024]
//   q = x@wq+bq; k = x@wk+bk; v = x@wv+bv
//   s = softmax(q @ k^T / 32)
//   out = (s @ v) @ wo + bo
// Round 1: fp32 SIMT tiled GEMM baseline (128x128x8, 8x8 per thread).
// ---------------------------------------------------------------------------

#define BATCH 4
#define SEQ   2048
#define DMODEL 1024
#define BM 128
#define BN 128
#define BK 8

// Scratch (allocation-free rule: __device__ globals)
__device__ float g_q[(long long)BATCH * SEQ * DMODEL];
__device__ float g_k[(long long)BATCH * SEQ * DMODEL];
__device__ float g_v[(long long)BATCH * SEQ * DMODEL];
__device__ float g_s[(long long)BATCH * SEQ * SEQ];
__device__ float g_o[(long long)BATCH * SEQ * DMODEL];

// C[M,N] = scale * (A[M,K] @ B) + bias,  B is [K,N] (NN) or [N,K] (NT).
// All of M,N divisible by 128, K divisible by 8 (guaranteed by shapes here).
template<bool TRANS_B, bool HAS_BIAS>
__global__ __launch_bounds__(256)
void gemm128(const float* __restrict__ A, const float* __restrict__ B,
             const float* __restrict__ bias, float* __restrict__ C,
             int M, int N, int K, float scale,
             long long sA, long long sB, long long sC)
{
    __shared__ float As[BK][BM];
    __shared__ float Bs[BK][BN];

    const int b = blockIdx.z;
    A += (long long)b * sA;
    B += (long long)b * sB;
    C += (long long)b * sC;

    const int m0 = blockIdx.y * BM;
    const int n0 = blockIdx.x * BN;
    const int t  = threadIdx.x;
    const int tx = t & 15;        // 0..15  -> N direction
    const int ty = t >> 4;        // 0..15  -> M direction

    float acc[8][8];
    #pragma unroll
    for (int i = 0; i < 8; i++)
        #pragma unroll
        for (int j = 0; j < 8; j++) acc[i][j] = 0.f;

    const int idx = t * 4;               // 1024 elements per tile / 256 thr
    const int a_m = idx >> 3;            // row within A tile
    const int a_k = idx & 7;             // k within A tile (multiple of 4)
    const int bn_k = idx >> 7;           // NN: k row of B tile
    const int bn_n = idx & 127;          // NN: col (multiple of 4)

    for (int k0 = 0; k0 < K; k0 += BK) {
        // --- load A tile (128 x 8), transpose into As[k][m] ---
        {
            float4 va = *(const float4*)&A[(long long)(m0 + a_m) * K + k0 + a_k];
            As[a_k + 0][a_m] = va.x;
            As[a_k + 1][a_m] = va.y;
            As[a_k + 2][a_m] = va.z;
            As[a_k + 3][a_m] = va.w;
        }
        // --- load B tile ---
        if (TRANS_B) {
            // B is [N,K] row-major; tile rows n0..n0+127, cols k0..k0+7
            float4 vb = *(const float4*)&B[(long long)(n0 + a_m) * K + k0 + a_k];
            Bs[a_k + 0][a_m] = vb.x;
            Bs[a_k + 1][a_m] = vb.y;
            Bs[a_k + 2][a_m] = vb.z;
            Bs[a_k + 3][a_m] = vb.w;
        } else {
            // B is [K,N] row-major; tile rows k0..k0+7, cols n0..n0+127
            float4 vb = *(const float4*)&B[(long long)(k0 + bn_k) * N + n0 + bn_n];
            *(float4*)&Bs[bn_k][bn_n] = vb;
        }
        __syncthreads();

        #pragma unroll
        for (int kk = 0; kk < BK; kk++) {
            float ar[8], br[8];
            *(float4*)&ar[0] = *(const float4*)&As[kk][ty * 4];
            *(float4*)&ar[4] = *(const float4*)&As[kk][64 + ty * 4];
            *(float4*)&br[0] = *(const float4*)&Bs[kk][tx * 4];
            *(float4*)&br[4] = *(const float4*)&Bs[kk][64 + tx * 4];
            #pragma unroll
            for (int i = 0; i < 8; i++)
                #pragma unroll
                for (int j = 0; j < 8; j++)
                    acc[i][j] += ar[i] * br[j];
        }
        __syncthreads();
    }

    // --- epilogue ---
    #pragma unroll
    for (int i = 0; i < 8; i++) {
        const int m = m0 + ((i < 4) ? (ty * 4 + i) : (64 + ty * 4 + i - 4));
        #pragma unroll
        for (int jh = 0; jh < 2; jh++) {
            const int n = n0 + ((jh == 0) ? (tx * 4) : (64 + tx * 4));
            float4 v;
            v.x = acc[i][jh * 4 + 0] * scale;
            v.y = acc[i][jh * 4 + 1] * scale;
            v.z = acc[i][jh * 4 + 2] * scale;
            v.w = acc[i][jh * 4 + 3] * scale;
            if (HAS_BIAS) {
                float4 bv = *(const float4*)&bias[n];
                v.x += bv.x; v.y += bv.y; v.z += bv.z; v.w += bv.w;
            }
            *(float4*)&C[(long long)m * N + n] = v;
        }
    }
}

// In-place softmax over rows of length 2048. One block (256 thr) per row.
__global__ __launch_bounds__(256)
void softmax2048(float* __restrict__ S)
{
    float* p = S + (long long)blockIdx.x * SEQ;
    const int t = threadIdx.x;

    float4 v0 = *(const float4*)&p[t * 4];
    float4 v1 = *(const float4*)&p[1024 + t * 4];

    float m = fmaxf(fmaxf(fmaxf(v0.x, v0.y), fmaxf(v0.z, v0.w)),
                    fmaxf(fmaxf(v1.x, v1.y), fmaxf(v1.z, v1.w)));
    #pragma unroll
    for (int o = 16; o; o >>= 1) m = fmaxf(m, __shfl_xor_sync(0xffffffffu, m, o));

    __shared__ float redm[8];
    __shared__ float reds[8];
    if ((t & 31) == 0) redm[t >> 5] = m;
    __syncthreads();
    m = redm[0];
    #pragma unroll
    for (int i = 1; i < 8; i++) m = fmaxf(m, redm[i]);

    v0.x = __expf(v0.x - m); v0.y = __expf(v0.y - m);
    v0.z = __expf(v0.z - m); v0.w = __expf(v0.w - m);
    v1.x = __expf(v1.x - m); v1.y = __expf(v1.y - m);
    v1.z = __expf(v1.z - m); v1.w = __expf(v1.w - m);

    float s = v0.x + v0.y + v0.z + v0.w + v1.x + v1.y + v1.z + v1.w;
    #pragma unroll
    for (int o = 16; o; o >>= 1) s += __shfl_xor_sync(0xffffffffu, s, o);
    if ((t & 31) == 0) reds[t >> 5] = s;
    __syncthreads();
    s = 0.f;
    #pragma unroll
    for (int i = 0; i < 8; i++) s += reds[i];

    const float inv = 1.f / s;
    v0.x *= inv; v0.y *= inv; v0.z *= inv; v0.w *= inv;
    v1.x *= inv; v1.y *= inv; v1.z *= inv; v1.w *= inv;
    *(float4*)&p[t * 4]        = v0;
    *(float4*)&p[1024 + t * 4] = v1;
}

extern "C" void kernel_launch(void* const* d_in, const int* in_sizes, int n_in,
                              void* d_out, int out_size)
{
    const float* x  = (const float*)d_in[0];
    const float* wq = (const float*)d_in[1];
    const float* bq = (const float*)d_in[2];
    const float* wk = (const float*)d_in[3];
    const float* bk = (const float*)d_in[4];
    const float* wv = (const float*)d_in[5];
    const float* bv = (const float*)d_in[6];
    const float* wo = (const float*)d_in[7];
    const float* bo = (const float*)d_in[8];
    float* out = (float*)d_out;

    float *q, *k, *v, *s, *o;
    cudaGetSymbolAddress((void**)&q, g_q);
    cudaGetSymbolAddress((void**)&k, g_k);
    cudaGetSymbolAddress((void**)&v, g_v);
    cudaGetSymbolAddress((void**)&s, g_s);
    cudaGetSymbolAddress((void**)&o, g_o);

    const int MTOT = BATCH * SEQ;              // 8192
    const float iscale = 0.03125f;             // 1/sqrt(1024)

    dim3 blk(256);
    dim3 gproj(DMODEL / BN, MTOT / BM, 1);     // (8, 64)

    // QKV projections
    gemm128<false, true><<<gproj, blk>>>(x, wq, bq, q, MTOT, DMODEL, DMODEL, 1.f, 0, 0, 0);
    gemm128<false, true><<<gproj, blk>>>(x, wk, bk, k, MTOT, DMODEL, DMODEL, 1.f, 0, 0, 0);
    gemm128<false, true><<<gproj, blk>>>(x, wv, bv, v, MTOT, DMODEL, DMODEL, 1.f, 0, 0, 0);

    // scores = q @ k^T * (1/32), batched over 4
    dim3 gsc(SEQ / BN, SEQ / BM, BATCH);       // (16, 16, 4)
    gemm128<true, false><<<gsc, blk>>>(q, k, nullptr, s, SEQ, SEQ, DMODEL, iscale,
                                       (long long)SEQ * DMODEL,
                                       (long long)SEQ * DMODEL,
                                       (long long)SEQ * SEQ);

    // softmax rows
    softmax2048<<<BATCH * SEQ, 256>>>(s);

    // o = s @ v, batched
    dim3 gav(DMODEL / BN, SEQ / BM, BATCH);    // (8, 16, 4)
    gemm128<false, false><<<gav, blk>>>(s, v, nullptr, o, SEQ, DMODEL, SEQ, 1.f,
                                        (long long)SEQ * SEQ,
                                        (long long)SEQ * DMODEL,
                                        (long long)SEQ * DMODEL);

    // out = o @ wo + bo
    gemm128<false, true><<<gproj, blk>>>(o, wo, bo, out, MTOT, DMODEL, DMODEL, 1.f, 0, 0, 0);
}

// round 2
// speedup vs baseline: 2.8362x; 2.8362x over previous
#include <cuda_runtime.h>
#include <cstdint>

// ---------------------------------------------------------------------------
// SelfAttention  x[4,2048,1024] -> out[4,2048,1024]
// Round 2: TF32 mma.sync (m16n8k8) tiled GEMMs, cp.async double buffering.
//   Accuracy: RNA-round all GEMM inputs to tf32 once (prepass / epilogues),
//   accumulate fp32.
// ---------------------------------------------------------------------------

#define BATCH 4
#define SEQ   2048
#define DM    1024

// ---- scratch (__device__ globals: allocation-free rule) ----
__device__ float g_x [(long long)BATCH * SEQ * DM];
__device__ float g_wq[DM * DM];
__device__ float g_wk[DM * DM];
__device__ float g_wv[DM * DM];
__device__ float g_wo[DM * DM];
__device__ float g_q [(long long)BATCH * SEQ * DM];
__device__ float g_k [(long long)BATCH * SEQ * DM];
__device__ float g_v [(long long)BATCH * SEQ * DM];
__device__ float g_s [(long long)BATCH * SEQ * SEQ];
__device__ float g_o [(long long)BATCH * SEQ * DM];

// ---- helpers ----
__device__ __forceinline__ float rna_tf32(float x) {
    float r; asm("cvt.rna.tf32.f32 %0, %1;" : "=f"(r) : "f"(x)); return r;
}

__device__ __forceinline__ void cp_async16(void* smem, const void* gmem) {
    uint32_t s = (uint32_t)__cvta_generic_to_shared(smem);
    asm volatile("cp.async.ca.shared.global [%0], [%1], 16;\n" :: "r"(s), "l"(gmem));
}
#define CP_COMMIT() asm volatile("cp.async.commit_group;\n" ::: "memory")
#define CP_WAIT1()  asm volatile("cp.async.wait_group 1;\n" ::: "memory")

__device__ __forceinline__ void mma_tf32(float* c, const uint32_t* a, const uint32_t* b) {
    asm volatile(
        "mma.sync.aligned.m16n8k8.row.col.f32.tf32.tf32.f32 "
        "{%0,%1,%2,%3}, {%4,%5,%6,%7}, {%8,%9}, {%0,%1,%2,%3};\n"
        : "+f"(c[0]), "+f"(c[1]), "+f"(c[2]), "+f"(c[3])
        : "r"(a[0]), "r"(a[1]), "r"(a[2]), "r"(a[3]), "r"(b[0]), "r"(b[1]));
}

// ---- prepass: round fp32 -> tf32 (rna) elementwise ----
__global__ __launch_bounds__(256)
void round_tf32_kernel(const float* __restrict__ in, float* __restrict__ out) {
    long long i = ((long long)blockIdx.x * 256 + threadIdx.x) * 4;
    float4 v = *(const float4*)(in + i);
    v.x = rna_tf32(v.x); v.y = rna_tf32(v.y);
    v.z = rna_tf32(v.z); v.w = rna_tf32(v.w);
    *(float4*)(out + i) = v;
}

// ---------------------------------------------------------------------------
// TF32 GEMM: C[M,N] = scale*(A[M,K] @ B) + bias
//   TRANS_B=0: B is [K,N] row-major.  TRANS_B=1: B is [N,K] row-major (B^T).
// CTA tile 128x256, BK=16, 256 threads, 8 warps (2 x 4), warp tile 64x64.
// ---------------------------------------------------------------------------
#define BM 128
#define BN 256
#define BK 16

template<bool TRANS_B, bool HAS_BIAS, bool EPI_ROUND>
__global__ __launch_bounds__(256, 1)
void gemm_tf32(const float* __restrict__ A, const float* __restrict__ B,
               const float* __restrict__ bias, float* __restrict__ C,
               int M, int N, int K, float scale,
               long long strA, long long strB, long long strC)
{
    extern __shared__ float smem[];
    constexpr int AST = BM * 20;                      // A stage: [128][16+4]
    constexpr int BST = TRANS_B ? BN * 20 : BK * 260; // B stage
    float* sA = smem;            // [2][AST]
    float* sB = smem + 2 * AST;  // [2][BST]

    const int bz = blockIdx.z;
    A += (long long)bz * strA;
    B += (long long)bz * strB;
    C += (long long)bz * strC;

    const int m0 = blockIdx.y * BM;
    const int n0 = blockIdx.x * BN;
    const int t    = threadIdx.x;
    const int lane = t & 31;
    const int wid  = t >> 5;
    const int warp_m = wid & 1;    // 0..1  (64 rows each)
    const int warp_n = wid >> 1;   // 0..3  (64 cols each)
    const int gid = lane >> 2;     // 0..7
    const int tig = lane & 3;      // 0..3

    float acc[4][8][4];
    #pragma unroll
    for (int mf = 0; mf < 4; mf++)
        #pragma unroll
        for (int nf = 0; nf < 8; nf++)
            #pragma unroll
            for (int r = 0; r < 4; r++) acc[mf][nf][r] = 0.f;

    const int ktiles = K / BK;

    // ---- tile loader ----
    auto load_tiles = [&](int stage, int kt) {
        const int k0 = kt * BK;
        float* dA = sA + stage * AST;
        float* dB = sB + stage * BST;
        #pragma unroll
        for (int i = 0; i < 2; i++) {               // A: 512 float4 chunks
            int ch = t + i * 256;
            int m = ch >> 2, kq = (ch & 3) * 4;
            cp_async16(dA + m * 20 + kq, A + (long long)(m0 + m) * K + k0 + kq);
        }
        #pragma unroll
        for (int i = 0; i < 4; i++) {               // B: 1024 float4 chunks
            int ch = t + i * 256;
            if (TRANS_B) {
                int n = ch >> 2, kq = (ch & 3) * 4;
                cp_async16(dB + n * 20 + kq, B + (long long)(n0 + n) * K + k0 + kq);
            } else {
                int k = ch >> 6, n4 = (ch & 63) * 4;
                cp_async16(dB + k * 260 + n4, B + (long long)(k0 + k) * N + n0 + n4);
            }
        }
    };

    load_tiles(0, 0);
    CP_COMMIT();

    for (int kt = 0; kt < ktiles; kt++) {
        const int cur = kt & 1;
        if (kt + 1 < ktiles) load_tiles(cur ^ 1, kt + 1);
        CP_COMMIT();
        CP_WAIT1();
        __syncthreads();

        const float* cA = sA + cur * AST;
        const float* cB = sB + cur * BST;

        #pragma unroll
        for (int kk = 0; kk < BK; kk += 8) {
            uint32_t af[4][4];
            #pragma unroll
            for (int mf = 0; mf < 4; mf++) {
                const float* p = cA + (warp_m * 64 + mf * 16 + gid) * 20 + kk + tig;
                af[mf][0] = __float_as_uint(p[0]);
                af[mf][1] = __float_as_uint(p[8 * 20]);
                af[mf][2] = __float_as_uint(p[4]);
                af[mf][3] = __float_as_uint(p[8 * 20 + 4]);
            }
            uint32_t bf[8][2];
            #pragma unroll
            for (int nf = 0; nf < 8; nf++) {
                if (TRANS_B) {
                    const float* p = cB + (warp_n * 64 + nf * 8 + gid) * 20 + kk + tig;
                    bf[nf][0] = __float_as_uint(p[0]);
                    bf[nf][1] = __float_as_uint(p[4]);
                } else {
                    const float* p = cB + (kk + tig) * 260 + warp_n * 64 + nf * 8 + gid;
                    bf[nf][0] = __float_as_uint(p[0]);
                    bf[nf][1] = __float_as_uint(p[4 * 260]);
                }
            }
            #pragma unroll
            for (int mf = 0; mf < 4; mf++)
                #pragma unroll
                for (int nf = 0; nf < 8; nf++)
                    mma_tf32(acc[mf][nf], af[mf], bf[nf]);
        }
        __syncthreads();
    }

    // ---- epilogue ----
    #pragma unroll
    for (int mf = 0; mf < 4; mf++) {
        const int r0 = m0 + warp_m * 64 + mf * 16 + gid;
        #pragma unroll
        for (int nf = 0; nf < 8; nf++) {
            const int n = n0 + warp_n * 64 + nf * 8 + 2 * tig;
            float bx = 0.f, by = 0.f;
            if (HAS_BIAS) {
                float2 bv = *(const float2*)&bias[n];
                bx = bv.x; by = bv.y;
            }
            float2 v0, v1;
            v0.x = acc[mf][nf][0] * scale + bx;
            v0.y = acc[mf][nf][1] * scale + by;
            v1.x = acc[mf][nf][2] * scale + bx;
            v1.y = acc[mf][nf][3] * scale + by;
            if (EPI_ROUND) {
                v0.x = rna_tf32(v0.x); v0.y = rna_tf32(v0.y);
                v1.x = rna_tf32(v1.x); v1.y = rna_tf32(v1.y);
            }
            *(float2*)&C[(long long)r0 * N + n]       = v0;
            *(float2*)&C[(long long)(r0 + 8) * N + n] = v1;
        }
    }
}

// ---- in-place softmax over rows of 2048, output rounded to tf32 ----
__global__ __launch_bounds__(256)
void softmax2048(float* __restrict__ S)
{
    float* p = S + (long long)blockIdx.x * SEQ;
    const int t = threadIdx.x;

    float4 v0 = *(const float4*)&p[t * 4];
    float4 v1 = *(const float4*)&p[1024 + t * 4];

    float m = fmaxf(fmaxf(fmaxf(v0.x, v0.y), fmaxf(v0.z, v0.w)),
                    fmaxf(fmaxf(v1.x, v1.y), fmaxf(v1.z, v1.w)));
    #pragma unroll
    for (int o = 16; o; o >>= 1) m = fmaxf(m, __shfl_xor_sync(0xffffffffu, m, o));

    __shared__ float redm[8];
    __shared__ float reds[8];
    if ((t & 31) == 0) redm[t >> 5] = m;
    __syncthreads();
    m = redm[0];
    #pragma unroll
    for (int i = 1; i < 8; i++) m = fmaxf(m, redm[i]);

    v0.x = __expf(v0.x - m); v0.y = __expf(v0.y - m);
    v0.z = __expf(v0.z - m); v0.w = __expf(v0.w - m);
    v1.x = __expf(v1.x - m); v1.y = __expf(v1.y - m);
    v1.z = __expf(v1.z - m); v1.w = __expf(v1.w - m);

    float s = v0.x + v0.y + v0.z + v0.w + v1.x + v1.y + v1.z + v1.w;
    #pragma unroll
    for (int o = 16; o; o >>= 1) s += __shfl_xor_sync(0xffffffffu, s, o);
    if ((t & 31) == 0) reds[t >> 5] = s;
    __syncthreads();
    s = 0.f;
    #pragma unroll
    for (int i = 0; i < 8; i++) s += reds[i];

    const float inv = 1.f / s;
    v0.x = rna_tf32(v0.x * inv); v0.y = rna_tf32(v0.y * inv);
    v0.z = rna_tf32(v0.z * inv); v0.w = rna_tf32(v0.w * inv);
    v1.x = rna_tf32(v1.x * inv); v1.y = rna_tf32(v1.y * inv);
    v1.z = rna_tf32(v1.z * inv); v1.w = rna_tf32(v1.w * inv);
    *(float4*)&p[t * 4]        = v0;
    *(float4*)&p[1024 + t * 4] = v1;
}

// ---------------------------------------------------------------------------
extern "C" void kernel_launch(void* const* d_in, const int* in_sizes, int n_in,
                              void* d_out, int out_size)
{
    const float* x  = (const float*)d_in[0];
    const float* wq = (const float*)d_in[1];
    const float* bq = (const float*)d_in[2];
    const float* wk = (const float*)d_in[3];
    const float* bk = (const float*)d_in[4];
    const float* wv = (const float*)d_in[5];
    const float* bv = (const float*)d_in[6];
    const float* wo = (const float*)d_in[7];
    const float* bo = (const float*)d_in[8];
    float* out = (float*)d_out;

    float *rx, *rwq, *rwk, *rwv, *rwo, *q, *k, *v, *s, *o;
    cudaGetSymbolAddress((void**)&rx,  g_x);
    cudaGetSymbolAddress((void**)&rwq, g_wq);
    cudaGetSymbolAddress((void**)&rwk, g_wk);
    cudaGetSymbolAddress((void**)&rwv, g_wv);
    cudaGetSymbolAddress((void**)&rwo, g_wo);
    cudaGetSymbolAddress((void**)&q,   g_q);
    cudaGetSymbolAddress((void**)&k,   g_k);
    cudaGetSymbolAddress((void**)&v,   g_v);
    cudaGetSymbolAddress((void**)&s,   g_s);
    cudaGetSymbolAddress((void**)&o,   g_o);

    const int MTOT = BATCH * SEQ;     // 8192
    const float iscale = 0.03125f;    // 1/sqrt(1024)

    const int SMEM_NN = (2 * BM * 20 + 2 * BK * 260) * 4;  // 53760 B
    const int SMEM_NT = (2 * BM * 20 + 2 * BN * 20) * 4;   // 61440 B
    cudaFuncSetAttribute(gemm_tf32<false, true,  true >, cudaFuncAttributeMaxDynamicSharedMemorySize, SMEM_NN);
    cudaFuncSetAttribute(gemm_tf32<false, true,  false>, cudaFuncAttributeMaxDynamicSharedMemorySize, SMEM_NN);
    cudaFuncSetAttribute(gemm_tf32<false, false, true >, cudaFuncAttributeMaxDynamicSharedMemorySize, SMEM_NN);
    cudaFuncSetAttribute(gemm_tf32<true,  false, false>, cudaFuncAttributeMaxDynamicSharedMemorySize, SMEM_NT);

    // --- prepass: round inputs to tf32 ---
    round_tf32_kernel<<<(long long)MTOT * DM / 1024, 256>>>(x,  rx);
    round_tf32_kernel<<<DM * DM / 1024, 256>>>(wq, rwq);
    round_tf32_kernel<<<DM * DM / 1024, 256>>>(wk, rwk);
    round_tf32_kernel<<<DM * DM / 1024, 256>>>(wv, rwv);
    round_tf32_kernel<<<DM * DM / 1024, 256>>>(wo, rwo);

    dim3 blk(256);
    dim3 gproj(DM / BN, MTOT / BM, 1);       // (4, 64)

    // QKV projections (epilogue rounds q,k,v to tf32)
    gemm_tf32<false, true, true><<<gproj, blk, SMEM_NN>>>(rx, rwq, bq, q, MTOT, DM, DM, 1.f, 0, 0, 0);
    gemm_tf32<false, true, true><<<gproj, blk, SMEM_NN>>>(rx, rwk, bk, k, MTOT, DM, DM, 1.f, 0, 0, 0);
    gemm_tf32<false, true, true><<<gproj, blk, SMEM_NN>>>(rx, rwv, bv, v, MTOT, DM, DM, 1.f, 0, 0, 0);

    // scores = q @ k^T * (1/32)
    dim3 gsc(SEQ / BN, SEQ / BM, BATCH);     // (8, 16, 4)
    gemm_tf32<true, false, false><<<gsc, blk, SMEM_NT>>>(q, k, nullptr, s, SEQ, SEQ, DM, iscale,
                                                         (long long)SEQ * DM,
                                                         (long long)SEQ * DM,
                                                         (long long)SEQ * SEQ);

    // softmax rows (output rounded to tf32)
    softmax2048<<<BATCH * SEQ, 256>>>(s);

    // o = s @ v  (epilogue rounds o)
    dim3 gav(DM / BN, SEQ / BM, BATCH);      // (4, 16, 4)
    gemm_tf32<false, false, true><<<gav, blk, SMEM_NN>>>(s, v, nullptr, o, SEQ, DM, SEQ, 1.f,
                                                         (long long)SEQ * SEQ,
                                                         (long long)SEQ * DM,
                                                         (long long)SEQ * DM);

    // out = o @ wo + bo (fp32 out, no round)
    gemm_tf32<false, true, false><<<gproj, blk, SMEM_NN>>>(o, rwo, bo, out, MTOT, DM, DM, 1.f, 0, 0, 0);
}

// round 4
// speedup vs baseline: 5.2446x; 1.8492x over previous
#include <cuda_runtime.h>
#include <cuda_fp16.h>
#include <cstdint>

// ---------------------------------------------------------------------------
// SelfAttention  x[4,2048,1024] -> out[4,2048,1024]
// Round 4: FP16 mma.sync m16n8k16 (fp32 accum), all GEMMs NT, cp.async
//          double-buffered. Scores kept fp32 through softmax for accuracy.
// (tcgen05 unavailable: harness ptxas targets sm_103, not sm_103a.)
// ---------------------------------------------------------------------------

#define BATCH 4
#define SEQ   2048
#define DM    1024

// ---- scratch (__device__ globals) ----
__device__ __half g_xh [(long long)BATCH * SEQ * DM];
__device__ __half g_wqt[DM * DM];
__device__ __half g_wkt[DM * DM];
__device__ __half g_wvt[DM * DM];
__device__ __half g_wot[DM * DM];
__device__ __half g_q  [(long long)BATCH * SEQ * DM];
__device__ __half g_k  [(long long)BATCH * SEQ * DM];
__device__ __half g_v  [(long long)BATCH * SEQ * DM];
__device__ __half g_vt [(long long)BATCH * SEQ * DM];
__device__ float  g_s  [(long long)BATCH * SEQ * SEQ];
__device__ __half g_p  [(long long)BATCH * SEQ * SEQ];
__device__ __half g_o  [(long long)BATCH * SEQ * DM];

// ---- PTX helpers ----
__device__ __forceinline__ void cp_async16(void* smem, const void* gmem) {
    uint32_t s = (uint32_t)__cvta_generic_to_shared(smem);
    asm volatile("cp.async.ca.shared.global [%0], [%1], 16;\n" :: "r"(s), "l"(gmem));
}
#define CP_COMMIT() asm volatile("cp.async.commit_group;\n" ::: "memory")
#define CP_WAIT1()  asm volatile("cp.async.wait_group 1;\n" ::: "memory")

__device__ __forceinline__ void mma_f16(float* c, const uint32_t* a, const uint32_t* b) {
    asm volatile(
        "mma.sync.aligned.m16n8k16.row.col.f32.f16.f16.f32 "
        "{%0,%1,%2,%3}, {%4,%5,%6,%7}, {%8,%9}, {%0,%1,%2,%3};\n"
        : "+f"(c[0]), "+f"(c[1]), "+f"(c[2]), "+f"(c[3])
        : "r"(a[0]), "r"(a[1]), "r"(a[2]), "r"(a[3]), "r"(b[0]), "r"(b[1]));
}

// ---------------------------------------------------------------------------
// FP16 NT GEMM: C[M,N] = scale*(A[M,K] @ B[N,K]^T) + bias
// CTA tile 128x256x32, 256 threads, 8 warps (2x4), warp tile 64x64.
// smem rows padded to 40 halves (80B) -> conflict-free fragment LDS.
// ---------------------------------------------------------------------------
#define BM 128
#define BN 256
#define BKH 32                   // K elems (half) per stage
#define PITCH 40                 // halves per smem row
#define ASTH (BM * PITCH)        // 5120 halves
#define BSTH (BN * PITCH)        // 10240 halves
#define GEMM_SMEM ((2 * ASTH + 2 * BSTH) * 2)   // 61440 bytes

template<bool HAS_BIAS, bool OUT_HALF>
__global__ __launch_bounds__(256, 1)
void gemm_h(const __half* __restrict__ A, const __half* __restrict__ B,
            const float* __restrict__ bias, void* __restrict__ Cv,
            int M, int N, int K, float scale,
            long long strA, long long strB, long long strC)
{
    extern __shared__ __half smem[];
    __half* sA = smem;                 // [2][ASTH]
    __half* sB = smem + 2 * ASTH;      // [2][BSTH]

    const int bz = blockIdx.z;
    A += (long long)bz * strA;
    B += (long long)bz * strB;

    const int m0 = blockIdx.y * BM;
    const int n0 = blockIdx.x * BN;
    const int t    = threadIdx.x;
    const int lane = t & 31;
    const int wid  = t >> 5;
    const int warp_m = wid & 1;     // 0..1
    const int warp_n = wid >> 1;    // 0..3
    const int gid = lane >> 2;      // 0..7
    const int tig = lane & 3;       // 0..3

    float acc[4][8][4];
    #pragma unroll
    for (int mf = 0; mf < 4; mf++)
        #pragma unroll
        for (int nf = 0; nf < 8; nf++)
            #pragma unroll
            for (int r = 0; r < 4; r++) acc[mf][nf][r] = 0.f;

    const int KT = K / BKH;

    auto load_tiles = [&](int stage, int kt) {
        const int k0 = kt * BKH;
        __half* dA = sA + stage * ASTH;
        __half* dB = sB + stage * BSTH;
        #pragma unroll
        for (int i = 0; i < 2; i++) {           // A: 512 16B chunks
            int ch = t + i * 256;
            int row = ch >> 2, c8 = (ch & 3) * 8;
            cp_async16(dA + row * PITCH + c8, A + (long long)(m0 + row) * K + k0 + c8);
        }
        #pragma unroll
        for (int i = 0; i < 4; i++) {           // B: 1024 16B chunks
            int ch = t + i * 256;
            int row = ch >> 2, c8 = (ch & 3) * 8;
            cp_async16(dB + row * PITCH + c8, B + (long long)(n0 + row) * K + k0 + c8);
        }
    };

    load_tiles(0, 0);
    CP_COMMIT();

    for (int kt = 0; kt < KT; kt++) {
        const int cur = kt & 1;
        if (kt + 1 < KT) load_tiles(cur ^ 1, kt + 1);
        CP_COMMIT();
        CP_WAIT1();
        __syncthreads();

        const __half* cA = sA + cur * ASTH;
        const __half* cB = sB + cur * BSTH;

        #pragma unroll
        for (int kk = 0; kk < BKH; kk += 16) {
            uint32_t af[4][4];
            #pragma unroll
            for (int mf = 0; mf < 4; mf++) {
                const __half* p = cA + (warp_m * 64 + mf * 16 + gid) * PITCH + kk + tig * 2;
                af[mf][0] = *(const uint32_t*)p;
                af[mf][1] = *(const uint32_t*)(p + 8 * PITCH);
                af[mf][2] = *(const uint32_t*)(p + 8);
                af[mf][3] = *(const uint32_t*)(p + 8 * PITCH + 8);
            }
            uint32_t bf[8][2];
            #pragma unroll
            for (int nf = 0; nf < 8; nf++) {
                const __half* p = cB + (warp_n * 64 + nf * 8 + gid) * PITCH + kk + tig * 2;
                bf[nf][0] = *(const uint32_t*)p;
                bf[nf][1] = *(const uint32_t*)(p + 8);
            }
            #pragma unroll
            for (int mf = 0; mf < 4; mf++)
                #pragma unroll
                for (int nf = 0; nf < 8; nf++)
                    mma_f16(acc[mf][nf], af[mf], bf[nf]);
        }
        __syncthreads();
    }

    // ---- epilogue ----
    #pragma unroll
    for (int mf = 0; mf < 4; mf++) {
        const int r0 = m0 + warp_m * 64 + mf * 16 + gid;
        #pragma unroll
        for (int nf = 0; nf < 8; nf++) {
            const int n = n0 + warp_n * 64 + nf * 8 + 2 * tig;
            float bx = 0.f, by = 0.f;
            if (HAS_BIAS) {
                float2 bv = *(const float2*)&bias[n];
                bx = bv.x; by = bv.y;
            }
            float c0 = acc[mf][nf][0] * scale + bx;
            float c1 = acc[mf][nf][1] * scale + by;
            float c2 = acc[mf][nf][2] * scale + bx;
            float c3 = acc[mf][nf][3] * scale + by;
            if (OUT_HALF) {
                __half* C = (__half*)Cv + (long long)bz * strC;
                *(__half2*)&C[(long long)r0 * N + n]       = __floats2half2_rn(c0, c1);
                *(__half2*)&C[(long long)(r0 + 8) * N + n] = __floats2half2_rn(c2, c3);
            } else {
                float* C = (float*)Cv + (long long)bz * strC;
                *(float2*)&C[(long long)r0 * N + n]       = make_float2(c0, c1);
                *(float2*)&C[(long long)(r0 + 8) * N + n] = make_float2(c2, c3);
            }
        }
    }
}

// ---- prepass: fp32 -> half convert (8 elems/thread) ----
__global__ __launch_bounds__(256)
void f2h_kernel(const float* __restrict__ in, __half* __restrict__ out) {
    long long i = ((long long)blockIdx.x * 256 + threadIdx.x) * 8;
    float4 a = *(const float4*)(in + i);
    float4 b = *(const float4*)(in + i + 4);
    __half2 h[4];
    h[0] = __floats2half2_rn(a.x, a.y);
    h[1] = __floats2half2_rn(a.z, a.w);
    h[2] = __floats2half2_rn(b.x, b.y);
    h[3] = __floats2half2_rn(b.z, b.w);
    *(uint4*)(out + i) = *(uint4*)h;
}

// ---- transpose fp32 [R,C] -> half [C,R] ----
__global__ __launch_bounds__(256)
void transpose_f2h(const float* __restrict__ in, __half* __restrict__ out, int R, int C)
{
    __shared__ float tl[32][33];
    const int c = blockIdx.x * 32 + threadIdx.x;
    const int r0 = blockIdx.y * 32;
    #pragma unroll
    for (int i = 0; i < 32; i += 8)
        tl[threadIdx.y + i][threadIdx.x] = in[(long long)(r0 + threadIdx.y + i) * C + c];
    __syncthreads();
    const int r2 = r0 + threadIdx.x;
    const int c2 = blockIdx.x * 32;
    #pragma unroll
    for (int i = 0; i < 32; i += 8)
        out[(long long)(c2 + threadIdx.y + i) * R + r2] = __float2half_rn(tl[threadIdx.x][threadIdx.y + i]);
}

// ---- transpose half [R,C] -> half [C,R], batched over z ----
__global__ __launch_bounds__(256)
void transpose_h(const __half* __restrict__ in, __half* __restrict__ out, int R, int C)
{
    __shared__ __half tl[32][34];
    const long long boff = (long long)blockIdx.z * R * C;
    in += boff; out += boff;
    const int c = blockIdx.x * 32 + threadIdx.x;
    const int r0 = blockIdx.y * 32;
    #pragma unroll
    for (int i = 0; i < 32; i += 8)
        tl[threadIdx.y + i][threadIdx.x] = in[(long long)(r0 + threadIdx.y + i) * C + c];
    __syncthreads();
    const int r2 = r0 + threadIdx.x;
    const int c2 = blockIdx.x * 32;
    #pragma unroll
    for (int i = 0; i < 32; i += 8)
        out[(long long)(c2 + threadIdx.y + i) * R + r2] = tl[threadIdx.x][threadIdx.y + i];
}

// ---- softmax: reads fp32 scores row (2048), writes half probs ----
__global__ __launch_bounds__(256)
void softmax2048(const float* __restrict__ S, __half* __restrict__ P)
{
    const float* p = S + (long long)blockIdx.x * SEQ;
    __half* ph = P + (long long)blockIdx.x * SEQ;
    const int t = threadIdx.x;
    float4 v0 = *(const float4*)&p[t * 4];
    float4 v1 = *(const float4*)&p[1024 + t * 4];
    float m = fmaxf(fmaxf(fmaxf(v0.x, v0.y), fmaxf(v0.z, v0.w)),
                    fmaxf(fmaxf(v1.x, v1.y), fmaxf(v1.z, v1.w)));
    #pragma unroll
    for (int o = 16; o; o >>= 1) m = fmaxf(m, __shfl_xor_sync(0xffffffffu, m, o));
    __shared__ float redm[8], reds[8];
    if ((t & 31) == 0) redm[t >> 5] = m;
    __syncthreads();
    m = redm[0];
    #pragma unroll
    for (int i = 1; i < 8; i++) m = fmaxf(m, redm[i]);
    v0.x = __expf(v0.x - m); v0.y = __expf(v0.y - m);
    v0.z = __expf(v0.z - m); v0.w = __expf(v0.w - m);
    v1.x = __expf(v1.x - m); v1.y = __expf(v1.y - m);
    v1.z = __expf(v1.z - m); v1.w = __expf(v1.w - m);
    float s = v0.x + v0.y + v0.z + v0.w + v1.x + v1.y + v1.z + v1.w;
    #pragma unroll
    for (int o = 16; o; o >>= 1) s += __shfl_xor_sync(0xffffffffu, s, o);
    if ((t & 31) == 0) reds[t >> 5] = s;
    __syncthreads();
    s = 0.f;
    #pragma unroll
    for (int i = 0; i < 8; i++) s += reds[i];
    const float inv = 1.f / s;
    __half2 h0[2], h1[2];
    h0[0] = __floats2half2_rn(v0.x * inv, v0.y * inv);
    h0[1] = __floats2half2_rn(v0.z * inv, v0.w * inv);
    h1[0] = __floats2half2_rn(v1.x * inv, v1.y * inv);
    h1[1] = __floats2half2_rn(v1.z * inv, v1.w * inv);
    *(uint2*)&ph[t * 4]        = *(uint2*)h0;
    *(uint2*)&ph[1024 + t * 4] = *(uint2*)h1;
}

// ---------------------------------------------------------------------------
extern "C" void kernel_launch(void* const* d_in, const int* in_sizes, int n_in,
                              void* d_out, int out_size)
{
    const float* x  = (const float*)d_in[0];
    const float* wq = (const float*)d_in[1];
    const float* bq = (const float*)d_in[2];
    const float* wk = (const float*)d_in[3];
    const float* bk = (const float*)d_in[4];
    const float* wv = (const float*)d_in[5];
    const float* bv = (const float*)d_in[6];
    const float* wo = (const float*)d_in[7];
    const float* bo = (const float*)d_in[8];
    float* out = (float*)d_out;

    __half *xh, *wqt, *wkt, *wvt, *wot, *q, *k, *v, *vt, *pm, *o;
    float* s;
    cudaGetSymbolAddress((void**)&xh,  g_xh);
    cudaGetSymbolAddress((void**)&wqt, g_wqt);
    cudaGetSymbolAddress((void**)&wkt, g_wkt);
    cudaGetSymbolAddress((void**)&wvt, g_wvt);
    cudaGetSymbolAddress((void**)&wot, g_wot);
    cudaGetSymbolAddress((void**)&q,   g_q);
    cudaGetSymbolAddress((void**)&k,   g_k);
    cudaGetSymbolAddress((void**)&v,   g_v);
    cudaGetSymbolAddress((void**)&vt,  g_vt);
    cudaGetSymbolAddress((void**)&s,   g_s);
    cudaGetSymbolAddress((void**)&pm,  g_p);
    cudaGetSymbolAddress((void**)&o,   g_o);

    cudaFuncSetAttribute(gemm_h<true,  true >, cudaFuncAttributeMaxDynamicSharedMemorySize, GEMM_SMEM);
    cudaFuncSetAttribute(gemm_h<false, false>, cudaFuncAttributeMaxDynamicSharedMemorySize, GEMM_SMEM);
    cudaFuncSetAttribute(gemm_h<false, true >, cudaFuncAttributeMaxDynamicSharedMemorySize, GEMM_SMEM);
    cudaFuncSetAttribute(gemm_h<true,  false>, cudaFuncAttributeMaxDynamicSharedMemorySize, GEMM_SMEM);

    const int MTOT = BATCH * SEQ;      // 8192
    const float iscale = 0.03125f;     // 1/sqrt(1024)

    // --- prepass: convert / transpose ---
    f2h_kernel<<<(long long)MTOT * DM / 2048, 256>>>(x, xh);
    dim3 tb(32, 8);
    transpose_f2h<<<dim3(32, 32, 1), tb>>>(wq, wqt, DM, DM);
    transpose_f2h<<<dim3(32, 32, 1), tb>>>(wk, wkt, DM, DM);
    transpose_f2h<<<dim3(32, 32, 1), tb>>>(wv, wvt, DM, DM);
    transpose_f2h<<<dim3(32, 32, 1), tb>>>(wo, wot, DM, DM);

    dim3 blk(256);
    dim3 gproj(DM / BN, MTOT / BM, 1);       // (4, 64)

    // QKV projections -> half
    gemm_h<true, true><<<gproj, blk, GEMM_SMEM>>>(xh, wqt, bq, q, MTOT, DM, DM, 1.f, 0, 0, 0);
    gemm_h<true, true><<<gproj, blk, GEMM_SMEM>>>(xh, wkt, bk, k, MTOT, DM, DM, 1.f, 0, 0, 0);
    gemm_h<true, true><<<gproj, blk, GEMM_SMEM>>>(xh, wvt, bv, v, MTOT, DM, DM, 1.f, 0, 0, 0);

    // v^T per batch: [2048,1024] -> [1024,2048]
    transpose_h<<<dim3(DM / 32, SEQ / 32, BATCH), tb>>>(v, vt, SEQ, DM);

    // scores = q @ k^T * (1/32) -> fp32
    dim3 gsc(SEQ / BN, SEQ / BM, BATCH);     // (8, 16, 4)
    gemm_h<false, false><<<gsc, blk, GEMM_SMEM>>>(q, k, nullptr, s, SEQ, SEQ, DM, iscale,
                                                  (long long)SEQ * DM,
                                                  (long long)SEQ * DM,
                                                  (long long)SEQ * SEQ);

    // softmax: fp32 scores -> half probs
    softmax2048<<<BATCH * SEQ, 256>>>(s, pm);

    // o = p @ v  (A = probs [S,S], B = v^T [D,S]) -> half
    dim3 gav(DM / BN, SEQ / BM, BATCH);      // (4, 16, 4)
    gemm_h<false, true><<<gav, blk, GEMM_SMEM>>>(pm, vt, nullptr, o, SEQ, DM, SEQ, 1.f,
                                                 (long long)SEQ * SEQ,
                                                 (long long)SEQ * DM,
                                                 (long long)SEQ * DM);

    // out = o @ wo + bo -> fp32
    gemm_h<true, false><<<gproj, blk, GEMM_SMEM>>>(o, wot, bo, out, MTOT, DM, DM, 1.f, 0, 0, 0);
}

// round 5
// speedup vs baseline: 5.8901x; 1.1231x over previous
#include <cuda_runtime.h>
#include <cuda_fp16.h>
#include <cstdint>

// ---------------------------------------------------------------------------
// SelfAttention  x[4,2048,1024] -> out[4,2048,1024]
// Round 5: FP16 mma.sync m16n8k16 + ldmatrix.x4 fragments + 4-stage cp.async
//          pipeline, one __syncthreads per k-tile. Scores fp32 thru softmax.
// ---------------------------------------------------------------------------

#define BATCH 4
#define SEQ   2048
#define DM    1024

// ---- scratch (__device__ globals) ----
__device__ __half g_xh [(long long)BATCH * SEQ * DM];
__device__ __half g_wqt[DM * DM];
__device__ __half g_wkt[DM * DM];
__device__ __half g_wvt[DM * DM];
__device__ __half g_wot[DM * DM];
__device__ __half g_q  [(long long)BATCH * SEQ * DM];
__device__ __half g_k  [(long long)BATCH * SEQ * DM];
__device__ __half g_v  [(long long)BATCH * SEQ * DM];
__device__ __half g_vt [(long long)BATCH * SEQ * DM];
__device__ float  g_s  [(long long)BATCH * SEQ * SEQ];
__device__ __half g_p  [(long long)BATCH * SEQ * SEQ];
__device__ __half g_o  [(long long)BATCH * SEQ * DM];

// ---- PTX helpers ----
__device__ __forceinline__ void cp_async16(void* smem, const void* gmem) {
    uint32_t s = (uint32_t)__cvta_generic_to_shared(smem);
    asm volatile("cp.async.ca.shared.global [%0], [%1], 16;\n" :: "r"(s), "l"(gmem));
}
#define CP_COMMIT() asm volatile("cp.async.commit_group;\n" ::: "memory")
#define CP_WAIT2()  asm volatile("cp.async.wait_group 2;\n" ::: "memory")

__device__ __forceinline__ void mma_f16(float* c, const uint32_t* a, const uint32_t* b) {
    asm volatile(
        "mma.sync.aligned.m16n8k16.row.col.f32.f16.f16.f32 "
        "{%0,%1,%2,%3}, {%4,%5,%6,%7}, {%8,%9}, {%0,%1,%2,%3};\n"
        : "+f"(c[0]), "+f"(c[1]), "+f"(c[2]), "+f"(c[3])
        : "r"(a[0]), "r"(a[1]), "r"(a[2]), "r"(a[3]), "r"(b[0]), "r"(b[1]));
}

__device__ __forceinline__ void ldmatrix_x4(uint32_t* r, uint32_t saddr) {
    asm volatile("ldmatrix.sync.aligned.m8n8.x4.shared.b16 {%0,%1,%2,%3}, [%4];"
        : "=r"(r[0]), "=r"(r[1]), "=r"(r[2]), "=r"(r[3]) : "r"(saddr));
}

// ---------------------------------------------------------------------------
// FP16 NT GEMM: C[M,N] = scale*(A[M,K] @ B[N,K]^T) + bias
// CTA 128x256x32, 256 thr, 8 warps (2x4), warp tile 64x64, 4-stage cp.async.
// ---------------------------------------------------------------------------
#define BM 128
#define BN 256
#define BKH 32                   // K halves per stage
#define PITCH 40                 // halves per smem row (80B: conflict-free)
#define ASTH (BM * PITCH)        // 5120 halves
#define BSTH (BN * PITCH)        // 10240 halves
#define STG_H (ASTH + BSTH)      // halves per stage
#define STAGES 4
#define GEMM_SMEM (STAGES * STG_H * 2)   // 122880 bytes

template<bool HAS_BIAS, bool OUT_HALF>
__global__ __launch_bounds__(256, 1)
void gemm_h(const __half* __restrict__ A, const __half* __restrict__ B,
            const float* __restrict__ bias, void* __restrict__ Cv,
            int M, int N, int K, float scale,
            long long strA, long long strB, long long strC)
{
    extern __shared__ __half smem[];
    const uint32_t sbase = (uint32_t)__cvta_generic_to_shared(smem);

    const int bz = blockIdx.z;
    A += (long long)bz * strA;
    B += (long long)bz * strB;

    const int m0 = blockIdx.y * BM;
    const int n0 = blockIdx.x * BN;
    const int t    = threadIdx.x;
    const int lane = t & 31;
    const int wid  = t >> 5;
    const int warp_m = wid & 1;     // 0..1
    const int warp_n = wid >> 1;    // 0..3
    const int gid = lane >> 2;      // 0..7
    const int tig = lane & 3;       // 0..3

    // ldmatrix per-lane source coords
    const int rowA = warp_m * 64 + (lane & 15);      // + mf*16
    const int colA = (lane >> 4) * 8;                // + kk
    const int gB   = lane >> 3;
    const int rowB = warp_n * 64 + (gB >> 1) * 8 + (lane & 7);  // + p*16
    const int colB = (gB & 1) * 8;                   // + kk

    float acc[4][8][4];
    #pragma unroll
    for (int mf = 0; mf < 4; mf++)
        #pragma unroll
        for (int nf = 0; nf < 8; nf++)
            #pragma unroll
            for (int r = 0; r < 4; r++) acc[mf][nf][r] = 0.f;

    const int KT = K / BKH;

    auto load_tiles = [&](int stage, int kt) {
        const int k0 = kt * BKH;
        __half* dA = smem + stage * STG_H;
        __half* dB = dA + ASTH;
        #pragma unroll
        for (int i = 0; i < 2; i++) {           // A: 512 16B chunks
            int ch = t + i * 256;
            int row = ch >> 2, c8 = (ch & 3) * 8;
            cp_async16(dA + row * PITCH + c8, A + (long long)(m0 + row) * K + k0 + c8);
        }
        #pragma unroll
        for (int i = 0; i < 4; i++) {           // B: 1024 16B chunks
            int ch = t + i * 256;
            int row = ch >> 2, c8 = (ch & 3) * 8;
            cp_async16(dB + row * PITCH + c8, B + (long long)(n0 + row) * K + k0 + c8);
        }
    };

    // prologue: stages 0..2
    #pragma unroll
    for (int p = 0; p < STAGES - 1; p++) {
        if (p < KT) load_tiles(p, p);
        CP_COMMIT();
    }

    for (int kt = 0; kt < KT; kt++) {
        CP_WAIT2();
        __syncthreads();          // stage kt ready; all warps done with kt-1

        if (kt + STAGES - 1 < KT) load_tiles((kt + STAGES - 1) & (STAGES - 1), kt + STAGES - 1);
        CP_COMMIT();

        const uint32_t aS = sbase + ((kt & (STAGES - 1)) * STG_H) * 2;
        const uint32_t bS = aS + ASTH * 2;

        #pragma unroll
        for (int kk = 0; kk < BKH; kk += 16) {
            uint32_t af[4][4];
            #pragma unroll
            for (int mf = 0; mf < 4; mf++)
                ldmatrix_x4(af[mf], aS + (uint32_t)(((rowA + mf * 16) * PITCH) + kk + colA) * 2);
            uint32_t bf[8][2];
            #pragma unroll
            for (int p = 0; p < 4; p++) {
                uint32_t r[4];
                ldmatrix_x4(r, bS + (uint32_t)(((rowB + p * 16) * PITCH) + kk + colB) * 2);
                bf[2 * p][0] = r[0]; bf[2 * p][1] = r[1];
                bf[2 * p + 1][0] = r[2]; bf[2 * p + 1][1] = r[3];
            }
            #pragma unroll
            for (int mf = 0; mf < 4; mf++)
                #pragma unroll
                for (int nf = 0; nf < 8; nf++)
                    mma_f16(acc[mf][nf], af[mf], bf[nf]);
        }
    }

    // ---- epilogue ----
    #pragma unroll
    for (int mf = 0; mf < 4; mf++) {
        const int r0 = m0 + warp_m * 64 + mf * 16 + gid;
        #pragma unroll
        for (int nf = 0; nf < 8; nf++) {
            const int n = n0 + warp_n * 64 + nf * 8 + 2 * tig;
            float bx = 0.f, by = 0.f;
            if (HAS_BIAS) {
                float2 bv = *(const float2*)&bias[n];
                bx = bv.x; by = bv.y;
            }
            float c0 = acc[mf][nf][0] * scale + bx;
            float c1 = acc[mf][nf][1] * scale + by;
            float c2 = acc[mf][nf][2] * scale + bx;
            float c3 = acc[mf][nf][3] * scale + by;
            if (OUT_HALF) {
                __half* C = (__half*)Cv + (long long)bz * strC;
                *(__half2*)&C[(long long)r0 * N + n]       = __floats2half2_rn(c0, c1);
                *(__half2*)&C[(long long)(r0 + 8) * N + n] = __floats2half2_rn(c2, c3);
            } else {
                float* C = (float*)Cv + (long long)bz * strC;
                *(float2*)&C[(long long)r0 * N + n]       = make_float2(c0, c1);
                *(float2*)&C[(long long)(r0 + 8) * N + n] = make_float2(c2, c3);
            }
        }
    }
}

// ---- prepass: fp32 -> half convert (8 elems/thread) ----
__global__ __launch_bounds__(256)
void f2h_kernel(const float* __restrict__ in, __half* __restrict__ out) {
    long long i = ((long long)blockIdx.x * 256 + threadIdx.x) * 8;
    float4 a = *(const float4*)(in + i);
    float4 b = *(const float4*)(in + i + 4);
    __half2 h[4];
    h[0] = __floats2half2_rn(a.x, a.y);
    h[1] = __floats2half2_rn(a.z, a.w);
    h[2] = __floats2half2_rn(b.x, b.y);
    h[3] = __floats2half2_rn(b.z, b.w);
    *(uint4*)(out + i) = *(uint4*)h;
}

// ---- transpose fp32 [R,C] -> half [C,R] ----
__global__ __launch_bounds__(256)
void transpose_f2h(const float* __restrict__ in, __half* __restrict__ out, int R, int C)
{
    __shared__ float tl[32][33];
    const int c = blockIdx.x * 32 + threadIdx.x;
    const int r0 = blockIdx.y * 32;
    #pragma unroll
    for (int i = 0; i < 32; i += 8)
        tl[threadIdx.y + i][threadIdx.x] = in[(long long)(r0 + threadIdx.y + i) * C + c];
    __syncthreads();
    const int r2 = r0 + threadIdx.x;
    const int c2 = blockIdx.x * 32;
    #pragma unroll
    for (int i = 0; i < 32; i += 8)
        out[(long long)(c2 + threadIdx.y + i) * R + r2] = __float2half_rn(tl[threadIdx.x][threadIdx.y + i]);
}

// ---- transpose half [R,C] -> half [C,R], batched over z ----
__global__ __launch_bounds__(256)
void transpose_h(const __half* __restrict__ in, __half* __restrict__ out, int R, int C)
{
    __shared__ __half tl[32][34];
    const long long boff = (long long)blockIdx.z * R * C;
    in += boff; out += boff;
    const int c = blockIdx.x * 32 + threadIdx.x;
    const int r0 = blockIdx.y * 32;
    #pragma unroll
    for (int i = 0; i < 32; i += 8)
        tl[threadIdx.y + i][threadIdx.x] = in[(long long)(r0 + threadIdx.y + i) * C + c];
    __syncthreads();
    const int r2 = r0 + threadIdx.x;
    const int c2 = blockIdx.x * 32;
    #pragma unroll
    for (int i = 0; i < 32; i += 8)
        out[(long long)(c2 + threadIdx.y + i) * R + r2] = tl[threadIdx.x][threadIdx.y + i];
}

// ---- softmax: reads fp32 scores row (2048), writes half probs ----
__global__ __launch_bounds__(256)
void softmax2048(const float* __restrict__ S, __half* __restrict__ P)
{
    const float* p = S + (long long)blockIdx.x * SEQ;
    __half* ph = P + (long long)blockIdx.x * SEQ;
    const int t = threadIdx.x;
    float4 v0 = *(const float4*)&p[t * 4];
    float4 v1 = *(const float4*)&p[1024 + t * 4];
    float m = fmaxf(fmaxf(fmaxf(v0.x, v0.y), fmaxf(v0.z, v0.w)),
                    fmaxf(fmaxf(v1.x, v1.y), fmaxf(v1.z, v1.w)));
    #pragma unroll
    for (int o = 16; o; o >>= 1) m = fmaxf(m, __shfl_xor_sync(0xffffffffu, m, o));
    __shared__ float redm[8], reds[8];
    if ((t & 31) == 0) redm[t >> 5] = m;
    __syncthreads();
    m = redm[0];
    #pragma unroll
    for (int i = 1; i < 8; i++) m = fmaxf(m, redm[i]);
    v0.x = __expf(v0.x - m); v0.y = __expf(v0.y - m);
    v0.z = __expf(v0.z - m); v0.w = __expf(v0.w - m);
    v1.x = __expf(v1.x - m); v1.y = __expf(v1.y - m);
    v1.z = __expf(v1.z - m); v1.w = __expf(v1.w - m);
    float s = v0.x + v0.y + v0.z + v0.w + v1.x + v1.y + v1.z + v1.w;
    #pragma unroll
    for (int o = 16; o; o >>= 1) s += __shfl_xor_sync(0xffffffffu, s, o);
    if ((t & 31) == 0) reds[t >> 5] = s;
    __syncthreads();
    s = 0.f;
    #pragma unroll
    for (int i = 0; i < 8; i++) s += reds[i];
    const float inv = 1.f / s;
    __half2 h0[2], h1[2];
    h0[0] = __floats2half2_rn(v0.x * inv, v0.y * inv);
    h0[1] = __floats2half2_rn(v0.z * inv, v0.w * inv);
    h1[0] = __floats2half2_rn(v1.x * inv, v1.y * inv);
    h1[1] = __floats2half2_rn(v1.z * inv, v1.w * inv);
    *(uint2*)&ph[t * 4]        = *(uint2*)h0;
    *(uint2*)&ph[1024 + t * 4] = *(uint2*)h1;
}

// ---------------------------------------------------------------------------
extern "C" void kernel_launch(void* const* d_in, const int* in_sizes, int n_in,
                              void* d_out, int out_size)
{
    const float* x  = (const float*)d_in[0];
    const float* wq = (const float*)d_in[1];
    const float* bq = (const float*)d_in[2];
    const float* wk = (const float*)d_in[3];
    const float* bk = (const float*)d_in[4];
    const float* wv = (const float*)d_in[5];
    const float* bv = (const float*)d_in[6];
    const float* wo = (const float*)d_in[7];
    const float* bo = (const float*)d_in[8];
    float* out = (float*)d_out;

    __half *xh, *wqt, *wkt, *wvt, *wot, *q, *k, *v, *vt, *pm, *o;
    float* s;
    cudaGetSymbolAddress((void**)&xh,  g_xh);
    cudaGetSymbolAddress((void**)&wqt, g_wqt);
    cudaGetSymbolAddress((void**)&wkt, g_wkt);
    cudaGetSymbolAddress((void**)&wvt, g_wvt);
    cudaGetSymbolAddress((void**)&wot, g_wot);
    cudaGetSymbolAddress((void**)&q,   g_q);
    cudaGetSymbolAddress((void**)&k,   g_k);
    cudaGetSymbolAddress((void**)&v,   g_v);
    cudaGetSymbolAddress((void**)&vt,  g_vt);
    cudaGetSymbolAddress((void**)&s,   g_s);
    cudaGetSymbolAddress((void**)&pm,  g_p);
    cudaGetSymbolAddress((void**)&o,   g_o);

    cudaFuncSetAttribute(gemm_h<true,  true >, cudaFuncAttributeMaxDynamicSharedMemorySize, GEMM_SMEM);
    cudaFuncSetAttribute(gemm_h<false, false>, cudaFuncAttributeMaxDynamicSharedMemorySize, GEMM_SMEM);
    cudaFuncSetAttribute(gemm_h<false, true >, cudaFuncAttributeMaxDynamicSharedMemorySize, GEMM_SMEM);
    cudaFuncSetAttribute(gemm_h<true,  false>, cudaFuncAttributeMaxDynamicSharedMemorySize, GEMM_SMEM);

    const int MTOT = BATCH * SEQ;      // 8192
    const float iscale = 0.03125f;     // 1/sqrt(1024)

    // --- prepass: convert / transpose ---
    f2h_kernel<<<(long long)MTOT * DM / 2048, 256>>>(x, xh);
    dim3 tb(32, 8);
    transpose_f2h<<<dim3(32, 32, 1), tb>>>(wq, wqt, DM, DM);
    transpose_f2h<<<dim3(32, 32, 1), tb>>>(wk, wkt, DM, DM);
    transpose_f2h<<<dim3(32, 32, 1), tb>>>(wv, wvt, DM, DM);
    transpose_f2h<<<dim3(32, 32, 1), tb>>>(wo, wot, DM, DM);

    dim3 blk(256);
    dim3 gproj(DM / BN, MTOT / BM, 1);       // (4, 64)

    // QKV projections -> half
    gemm_h<true, true><<<gproj, blk, GEMM_SMEM>>>(xh, wqt, bq, q, MTOT, DM, DM, 1.f, 0, 0, 0);
    gemm_h<true, true><<<gproj, blk, GEMM_SMEM>>>(xh, wkt, bk, k, MTOT, DM, DM, 1.f, 0, 0, 0);
    gemm_h<true, true><<<gproj, blk, GEMM_SMEM>>>(xh, wvt, bv, v, MTOT, DM, DM, 1.f, 0, 0, 0);

    // v^T per batch: [2048,1024] -> [1024,2048]
    transpose_h<<<dim3(DM / 32, SEQ / 32, BATCH), tb>>>(v, vt, SEQ, DM);

    // scores = q @ k^T * (1/32) -> fp32
    dim3 gsc(SEQ / BN, SEQ / BM, BATCH);     // (8, 16, 4)
    gemm_h<false, false><<<gsc, blk, GEMM_SMEM>>>(q, k, nullptr, s, SEQ, SEQ, DM, iscale,
                                                  (long long)SEQ * DM,
                                                  (long long)SEQ * DM,
                                                  (long long)SEQ * SEQ);

    // softmax: fp32 scores -> half probs
    softmax2048<<<BATCH * SEQ, 256>>>(s, pm);

    // o = p @ v  (A = probs [S,S], B = v^T [D,S]) -> half
    dim3 gav(DM / BN, SEQ / BM, BATCH);      // (4, 16, 4)
    gemm_h<false, true><<<gav, blk, GEMM_SMEM>>>(pm, vt, nullptr, o, SEQ, DM, SEQ, 1.f,
                                                 (long long)SEQ * SEQ,
                                                 (long long)SEQ * DM,
                                                 (long long)SEQ * DM);

    // out = o @ wo + bo -> fp32
    gemm_h<true, false><<<gproj, blk, GEMM_SMEM>>>(o, wot, bo, out, MTOT, DM, DM, 1.f, 0, 0, 0);
}

// round 6
// speedup vs baseline: 7.1982x; 1.2221x over previous
#include <cuda_runtime.h>
#include <cuda_fp16.h>
#include <cstdint>

// ---------------------------------------------------------------------------
// SelfAttention  x[4,2048,1024] -> out[4,2048,1024]
// Round 6: FP16 mma.sync + ldmatrix, BK=64 3-stage cp.async pipeline,
//          fused QKV projection (N=3072, routed epilogue), launch diet.
// ---------------------------------------------------------------------------

#define BATCH 4
#define SEQ   2048
#define DM    1024

// ---- scratch (__device__ globals) ----
__device__ __half g_xh   [(long long)BATCH * SEQ * DM];
__device__ __half g_wqkvt[3 * DM * DM];
__device__ __half g_wot  [DM * DM];
__device__ float  g_bqkv [3 * DM];
__device__ __half g_q  [(long long)BATCH * SEQ * DM];
__device__ __half g_k  [(long long)BATCH * SEQ * DM];
__device__ __half g_v  [(long long)BATCH * SEQ * DM];
__device__ __half g_vt [(long long)BATCH * SEQ * DM];
__device__ float  g_s  [(long long)BATCH * SEQ * SEQ];
__device__ __half g_p  [(long long)BATCH * SEQ * SEQ];
__device__ __half g_o  [(long long)BATCH * SEQ * DM];

// ---- PTX helpers ----
__device__ __forceinline__ void cp_async16(void* smem, const void* gmem) {
    uint32_t s = (uint32_t)__cvta_generic_to_shared(smem);
    asm volatile("cp.async.ca.shared.global [%0], [%1], 16;\n" :: "r"(s), "l"(gmem));
}
#define CP_COMMIT() asm volatile("cp.async.commit_group;\n" ::: "memory")
#define CP_WAIT1()  asm volatile("cp.async.wait_group 1;\n" ::: "memory")

__device__ __forceinline__ void mma_f16(float* c, const uint32_t* a, const uint32_t* b) {
    asm volatile(
        "mma.sync.aligned.m16n8k16.row.col.f32.f16.f16.f32 "
        "{%0,%1,%2,%3}, {%4,%5,%6,%7}, {%8,%9}, {%0,%1,%2,%3};\n"
        : "+f"(c[0]), "+f"(c[1]), "+f"(c[2]), "+f"(c[3])
        : "r"(a[0]), "r"(a[1]), "r"(a[2]), "r"(a[3]), "r"(b[0]), "r"(b[1]));
}

__device__ __forceinline__ void ldmatrix_x4(uint32_t* r, uint32_t saddr) {
    asm volatile("ldmatrix.sync.aligned.m8n8.x4.shared.b16 {%0,%1,%2,%3}, [%4];"
        : "=r"(r[0]), "=r"(r[1]), "=r"(r[2]), "=r"(r[3]) : "r"(saddr));
}

// ---------------------------------------------------------------------------
// FP16 NT GEMM: C = scale*(A[M,K] @ B[N,K]^T) + bias
// CTA 128x256x64, 256 thr, 8 warps (2x4), warp tile 64x64, 3-stage cp.async.
// MODE: 0=QKV (half out, bias, route by n-block), 1=scores (f32, scale),
//       2=PV (half), 3=outproj (f32, bias)
// ---------------------------------------------------------------------------
#define BM 128
#define BN 256
#define BKH 64                   // K halves per stage
#define PITCH 72                 // halves per smem row (144B: conflict-free)
#define ASTH (BM * PITCH)        // 9216 halves
#define BSTH (BN * PITCH)        // 18432 halves
#define STG_H (ASTH + BSTH)      // 27648 halves per stage
#define STAGES 3
#define GEMM_SMEM (STAGES * STG_H * 2)   // 165888 bytes

template<int MODE>
__global__ __launch_bounds__(256, 1)
void gemm_h(const __half* __restrict__ A, const __half* __restrict__ B,
            const float* __restrict__ bias,
            void* __restrict__ C0, void* __restrict__ C1, void* __restrict__ C2,
            int N, int K, float scale,
            long long strA, long long strB, long long strC)
{
    extern __shared__ __half smem[];
    const uint32_t sbase = (uint32_t)__cvta_generic_to_shared(smem);

    const int bz = blockIdx.z;
    A += (long long)bz * strA;
    B += (long long)bz * strB;

    const int m0 = blockIdx.y * BM;
    const int n0 = blockIdx.x * BN;
    const int t    = threadIdx.x;
    const int lane = t & 31;
    const int wid  = t >> 5;
    const int warp_m = wid & 1;
    const int warp_n = wid >> 1;
    const int gid = lane >> 2;
    const int tig = lane & 3;

    // ldmatrix per-lane source coords
    const int rowA = warp_m * 64 + (lane & 15);
    const int colA = (lane >> 4) * 8;
    const int gB   = lane >> 3;
    const int rowB = warp_n * 64 + (gB >> 1) * 8 + (lane & 7);
    const int colB = (gB & 1) * 8;

    float acc[4][8][4];
    #pragma unroll
    for (int mf = 0; mf < 4; mf++)
        #pragma unroll
        for (int nf = 0; nf < 8; nf++)
            #pragma unroll
            for (int r = 0; r < 4; r++) acc[mf][nf][r] = 0.f;

    const int KT = K / BKH;

    auto load_tiles = [&](int stage, int kt) {
        const int k0 = kt * BKH;
        __half* dA = smem + stage * STG_H;
        __half* dB = dA + ASTH;
        #pragma unroll
        for (int i = 0; i < 4; i++) {           // A: 1024 16B chunks
            int ch = t + i * 256;
            int row = ch >> 3, c8 = (ch & 7) * 8;
            cp_async16(dA + row * PITCH + c8, A + (long long)(m0 + row) * K + k0 + c8);
        }
        #pragma unroll
        for (int i = 0; i < 8; i++) {           // B: 2048 16B chunks
            int ch = t + i * 256;
            int row = ch >> 3, c8 = (ch & 7) * 8;
            cp_async16(dB + row * PITCH + c8, B + (long long)(n0 + row) * K + k0 + c8);
        }
    };

    // prologue: stages 0,1
    load_tiles(0, 0); CP_COMMIT();
    if (1 < KT) load_tiles(1, 1);
    CP_COMMIT();

    int stage = 0;
    for (int kt = 0; kt < KT; kt++) {
        CP_WAIT1();
        __syncthreads();          // stage kt ready; all warps done with kt-1

        if (kt + 2 < KT) {
            int ns = stage + 2; if (ns >= STAGES) ns -= STAGES;
            load_tiles(ns, kt + 2);
        }
        CP_COMMIT();

        const uint32_t aS = sbase + (stage * STG_H) * 2;
        const uint32_t bS = aS + ASTH * 2;

        #pragma unroll
        for (int kk = 0; kk < BKH; kk += 16) {
            uint32_t af[4][4];
            #pragma unroll
            for (int mf = 0; mf < 4; mf++)
                ldmatrix_x4(af[mf], aS + (uint32_t)(((rowA + mf * 16) * PITCH) + kk + colA) * 2);
            uint32_t bf[8][2];
            #pragma unroll
            for (int p = 0; p < 4; p++) {
                uint32_t r[4];
                ldmatrix_x4(r, bS + (uint32_t)(((rowB + p * 16) * PITCH) + kk + colB) * 2);
                bf[2 * p][0] = r[0]; bf[2 * p][1] = r[1];
                bf[2 * p + 1][0] = r[2]; bf[2 * p + 1][1] = r[3];
            }
            #pragma unroll
            for (int mf = 0; mf < 4; mf++)
                #pragma unroll
                for (int nf = 0; nf < 8; nf++)
                    mma_f16(acc[mf][nf], af[mf], bf[nf]);
        }
        if (++stage >= STAGES) stage = 0;
    }

    // ---- epilogue ----
    // Output routing
    __half* Ch; float* Cf; int Nout = N;
    int ncol0 = n0;
    if (MODE == 0) {            // QKV: route by 1024-block
        const int blk = n0 >> 10;
        Ch = (__half*)(blk == 0 ? C0 : (blk == 1 ? C1 : C2));
        Ch += (long long)bz * strC;
        ncol0 = n0 & 1023; Nout = DM;
    } else if (MODE == 2) {
        Ch = (__half*)C0 + (long long)bz * strC;
    } else {
        Cf = (float*)C0 + (long long)bz * strC;
    }

    #pragma unroll
    for (int mf = 0; mf < 4; mf++) {
        const int r0 = m0 + warp_m * 64 + mf * 16 + gid;
        #pragma unroll
        for (int nf = 0; nf < 8; nf++) {
            const int nrel = warp_n * 64 + nf * 8 + 2 * tig;
            const int n = ncol0 + nrel;
            float bx = 0.f, by = 0.f;
            if (MODE == 0 || MODE == 3) {
                float2 bv = *(const float2*)&bias[n0 + nrel];  // global-n bias (concat for QKV)
                bx = bv.x; by = bv.y;
            }
            float c0 = acc[mf][nf][0] * scale + bx;
            float c1 = acc[mf][nf][1] * scale + by;
            float c2 = acc[mf][nf][2] * scale + bx;
            float c3 = acc[mf][nf][3] * scale + by;
            if (MODE == 0 || MODE == 2) {
                *(__half2*)&Ch[(long long)r0 * Nout + n]       = __floats2half2_rn(c0, c1);
                *(__half2*)&Ch[(long long)(r0 + 8) * Nout + n] = __floats2half2_rn(c2, c3);
            } else {
                *(float2*)&Cf[(long long)r0 * Nout + n]       = make_float2(c0, c1);
                *(float2*)&Cf[(long long)(r0 + 8) * Nout + n] = make_float2(c2, c3);
            }
        }
    }
}

// ---- prepass: fp32 -> half convert (8 elems/thread) ----
__global__ __launch_bounds__(256)
void f2h_kernel(const float* __restrict__ in, __half* __restrict__ out) {
    long long i = ((long long)blockIdx.x * 256 + threadIdx.x) * 8;
    float4 a = *(const float4*)(in + i);
    float4 b = *(const float4*)(in + i + 4);
    __half2 h[4];
    h[0] = __floats2half2_rn(a.x, a.y);
    h[1] = __floats2half2_rn(a.z, a.w);
    h[2] = __floats2half2_rn(b.x, b.y);
    h[3] = __floats2half2_rn(b.z, b.w);
    *(uint4*)(out + i) = *(uint4*)h;
}

// ---- batched weight transpose: z selects which weight ----
struct WBatch { const float* in[4]; __half* out[4]; };

__global__ __launch_bounds__(256)
void transpose_w4(WBatch wb)
{
    __shared__ float tl[32][33];
    const float* in = wb.in[blockIdx.z];
    __half* out = wb.out[blockIdx.z];
    const int R = DM, C = DM;
    const int c = blockIdx.x * 32 + threadIdx.x;
    const int r0 = blockIdx.y * 32;
    #pragma unroll
    for (int i = 0; i < 32; i += 8)
        tl[threadIdx.y + i][threadIdx.x] = in[(long long)(r0 + threadIdx.y + i) * C + c];
    __syncthreads();
    const int r2 = r0 + threadIdx.x;
    const int c2 = blockIdx.x * 32;
    #pragma unroll
    for (int i = 0; i < 32; i += 8)
        out[(long long)(c2 + threadIdx.y + i) * R + r2] = __float2half_rn(tl[threadIdx.x][threadIdx.y + i]);
}

// ---- bias concat [3*DM] ----
__global__ __launch_bounds__(256)
void bias_cat(const float* __restrict__ bq, const float* __restrict__ bk,
              const float* __restrict__ bv, float* __restrict__ out)
{
    int i = blockIdx.x * 256 + threadIdx.x;
    const float* src = (i < DM) ? bq : (i < 2 * DM ? bk : bv);
    out[i] = src[i & (DM - 1)];
}

// ---- transpose half [R,C] -> half [C,R], batched over z ----
__global__ __launch_bounds__(256)
void transpose_h(const __half* __restrict__ in, __half* __restrict__ out, int R, int C)
{
    __shared__ __half tl[32][34];
    const long long boff = (long long)blockIdx.z * R * C;
    in += boff; out += boff;
    const int c = blockIdx.x * 32 + threadIdx.x;
    const int r0 = blockIdx.y * 32;
    #pragma unroll
    for (int i = 0; i < 32; i += 8)
        tl[threadIdx.y + i][threadIdx.x] = in[(long long)(r0 + threadIdx.y + i) * C + c];
    __syncthreads();
    const int r2 = r0 + threadIdx.x;
    const int c2 = blockIdx.x * 32;
    #pragma unroll
    for (int i = 0; i < 32; i += 8)
        out[(long long)(c2 + threadIdx.y + i) * R + r2] = tl[threadIdx.x][threadIdx.y + i];
}

// ---- softmax: fp32 scores row (2048) -> half probs ----
__global__ __launch_bounds__(256)
void softmax2048(const float* __restrict__ S, __half* __restrict__ P)
{
    const float* p = S + (long long)blockIdx.x * SEQ;
    __half* ph = P + (long long)blockIdx.x * SEQ;
    const int t = threadIdx.x;
    float4 v0 = *(const float4*)&p[t * 4];
    float4 v1 = *(const float4*)&p[1024 + t * 4];
    float m = fmaxf(fmaxf(fmaxf(v0.x, v0.y), fmaxf(v0.z, v0.w)),
                    fmaxf(fmaxf(v1.x, v1.y), fmaxf(v1.z, v1.w)));
    #pragma unroll
    for (int o = 16; o; o >>= 1) m = fmaxf(m, __shfl_xor_sync(0xffffffffu, m, o));
    __shared__ float redm[8], reds[8];
    if ((t & 31) == 0) redm[t >> 5] = m;
    __syncthreads();
    m = redm[0];
    #pragma unroll
    for (int i = 1; i < 8; i++) m = fmaxf(m, redm[i]);
    v0.x = __expf(v0.x - m); v0.y = __expf(v0.y - m);
    v0.z = __expf(v0.z - m); v0.w = __expf(v0.w - m);
    v1.x = __expf(v1.x - m); v1.y = __expf(v1.y - m);
    v1.z = __expf(v1.z - m); v1.w = __expf(v1.w - m);
    float s = v0.x + v0.y + v0.z + v0.w + v1.x + v1.y + v1.z + v1.w;
    #pragma unroll
    for (int o = 16; o; o >>= 1) s += __shfl_xor_sync(0xffffffffu, s, o);
    if ((t & 31) == 0) reds[t >> 5] = s;
    __syncthreads();
    s = 0.f;
    #pragma unroll
    for (int i = 0; i < 8; i++) s += reds[i];
    const float inv = 1.f / s;
    __half2 h0[2], h1[2];
    h0[0] = __floats2half2_rn(v0.x * inv, v0.y * inv);
    h0[1] = __floats2half2_rn(v0.z * inv, v0.w * inv);
    h1[0] = __floats2half2_rn(v1.x * inv, v1.y * inv);
    h1[1] = __floats2half2_rn(v1.z * inv, v1.w * inv);
    *(uint2*)&ph[t * 4]        = *(uint2*)h0;
    *(uint2*)&ph[1024 + t * 4] = *(uint2*)h1;
}

// ---------------------------------------------------------------------------
extern "C" void kernel_launch(void* const* d_in, const int* in_sizes, int n_in,
                              void* d_out, int out_size)
{
    const float* x  = (const float*)d_in[0];
    const float* wq = (const float*)d_in[1];
    const float* bq = (const float*)d_in[2];
    const float* wk = (const float*)d_in[3];
    const float* bk = (const float*)d_in[4];
    const float* wv = (const float*)d_in[5];
    const float* bv = (const float*)d_in[6];
    const float* wo = (const float*)d_in[7];
    const float* bo = (const float*)d_in[8];
    float* out = (float*)d_out;

    __half *xh, *wqkvt, *wot, *q, *k, *v, *vt, *pm, *o;
    float *s, *bqkv;
    cudaGetSymbolAddress((void**)&xh,    g_xh);
    cudaGetSymbolAddress((void**)&wqkvt, g_wqkvt);
    cudaGetSymbolAddress((void**)&wot,   g_wot);
    cudaGetSymbolAddress((void**)&bqkv,  g_bqkv);
    cudaGetSymbolAddress((void**)&q,   g_q);
    cudaGetSymbolAddress((void**)&k,   g_k);
    cudaGetSymbolAddress((void**)&v,   g_v);
    cudaGetSymbolAddress((void**)&vt,  g_vt);
    cudaGetSymbolAddress((void**)&s,   g_s);
    cudaGetSymbolAddress((void**)&pm,  g_p);
    cudaGetSymbolAddress((void**)&o,   g_o);

    cudaFuncSetAttribute(gemm_h<0>, cudaFuncAttributeMaxDynamicSharedMemorySize, GEMM_SMEM);
    cudaFuncSetAttribute(gemm_h<1>, cudaFuncAttributeMaxDynamicSharedMemorySize, GEMM_SMEM);
    cudaFuncSetAttribute(gemm_h<2>, cudaFuncAttributeMaxDynamicSharedMemorySize, GEMM_SMEM);
    cudaFuncSetAttribute(gemm_h<3>, cudaFuncAttributeMaxDynamicSharedMemorySize, GEMM_SMEM);

    const int MTOT = BATCH * SEQ;      // 8192
    const float iscale = 0.03125f;     // 1/sqrt(1024)

    // --- prepass ---
    f2h_kernel<<<(long long)MTOT * DM / 2048, 256>>>(x, xh);
    WBatch wb;
    wb.in[0] = wq; wb.in[1] = wk; wb.in[2] = wv; wb.in[3] = wo;
    wb.out[0] = wqkvt; wb.out[1] = wqkvt + DM * DM; wb.out[2] = wqkvt + 2 * DM * DM;
    wb.out[3] = wot;
    transpose_w4<<<dim3(32, 32, 4), dim3(32, 8)>>>(wb);
    bias_cat<<<3 * DM / 256, 256>>>(bq, bk, bv, bqkv);

    dim3 blk(256);

    // fused QKV projection: N=3072, routed epilogue
    dim3 gqkv(3 * DM / BN, MTOT / BM, 1);    // (12, 64)
    gemm_h<0><<<gqkv, blk, GEMM_SMEM>>>(xh, wqkvt, bqkv, q, k, v,
                                        3 * DM, DM, 1.f, 0, 0, 0);

    // v^T per batch
    transpose_h<<<dim3(DM / 32, SEQ / 32, BATCH), dim3(32, 8)>>>(v, vt, SEQ, DM);

    // scores = q @ k^T * (1/32) -> fp32
    dim3 gsc(SEQ / BN, SEQ / BM, BATCH);     // (8, 16, 4)
    gemm_h<1><<<gsc, blk, GEMM_SMEM>>>(q, k, nullptr, s, nullptr, nullptr,
                                       SEQ, DM, iscale,
                                       (long long)SEQ * DM, (long long)SEQ * DM,
                                       (long long)SEQ * SEQ);

    // softmax: fp32 scores -> half probs
    softmax2048<<<BATCH * SEQ, 256>>>(s, pm);

    // o = p @ v  (A = probs, B = v^T) -> half
    dim3 gav(DM / BN, SEQ / BM, BATCH);      // (4, 16, 4)
    gemm_h<2><<<gav, blk, GEMM_SMEM>>>(pm, vt, nullptr, o, nullptr, nullptr,
                                       DM, SEQ, 1.f,
                                       (long long)SEQ * SEQ, (long long)SEQ * DM,
                                       (long long)SEQ * DM);

    // out = o @ wo + bo -> fp32
    dim3 gop(DM / BN, MTOT / BM, 1);         // (4, 64)
    gemm_h<3><<<gop, blk, GEMM_SMEM>>>(o, wot, bo, out, nullptr, nullptr,
                                       DM, DM, 1.f, 0, 0, 0);
}